// round 10
// baseline (speedup 1.0000x reference)
#include <cuda_runtime.h>
#include <cuda_bf16.h>
#include <math.h>
#include <stdint.h>

#define NN 50000
#define EE 600000
#define HH 128
#define GG 64
#define PCH 64
#define DCAP 64
#define NTILES 391   // ceil(50000/128)

// ---- static device scratch ----
__device__ float g_bufA[(size_t)NN * HH];
__device__ float g_pool[GG * HH];
__device__ int   g_deg[3 * NN];                 // zeroed at load; re-zeroed by pool_kernel
__device__ int   g_csr[(size_t)3 * NN * DCAP];
__device__ __nv_bfloat16 g_hH[2][(size_t)NN * HH];
__device__ __nv_bfloat16 g_hL[2][(size_t)NN * HH];
__device__ __nv_bfloat16 g_aggH[(size_t)NN * HH];
__device__ __nv_bfloat16 g_aggL[(size_t)NN * HH];
// weights bf16: [conv 5][phase 2][hi/lo 2][n=128][k=128]
__device__ __nv_bfloat16 g_wtb[5 * 4 * HH * HH];

// ================= helpers =================
__device__ __forceinline__ uint32_t s2u(const void* p) {
    uint32_t a;
    asm("{ .reg .u64 t; cvta.to.shared.u64 t, %1; cvt.u32.u64 %0, t; }" : "=r"(a) : "l"(p));
    return a;
}
__device__ __forceinline__ void cpa16(uint32_t d, const void* s, uint32_t ssz) {
    asm volatile("cp.async.cg.shared.global [%0], [%1], 16, %2;"
                 :: "r"(d), "l"(s), "r"(ssz) : "memory");
}
__device__ __forceinline__ void cpa_commit() {
    asm volatile("cp.async.commit_group;" ::: "memory");
}
template <int N>
__device__ __forceinline__ void cpa_wait() {
    asm volatile("cp.async.wait_group %0;" :: "n"(N) : "memory");
}
#define LDSM4(r0, r1, r2, r3, a) \
    asm volatile("ldmatrix.sync.aligned.m8n8.x4.shared.b16 {%0,%1,%2,%3}, [%4];" \
                 : "=r"(r0), "=r"(r1), "=r"(r2), "=r"(r3) : "r"(a))
#define MMA_BF16(c, a, b) \
    asm volatile("mma.sync.aligned.m16n8k16.row.col.f32.bf16.bf16.f32 " \
                 "{%0,%1,%2,%3},{%4,%5,%6,%7},{%8,%9},{%0,%1,%2,%3};" \
                 : "+f"((c)[0]), "+f"((c)[1]), "+f"((c)[2]), "+f"((c)[3]) \
                 : "r"((a)[0]), "r"((a)[1]), "r"((a)[2]), "r"((a)[3]), \
                   "r"((b)[0]), "r"((b)[1]))

// smem: B 4x32KB @0, A 3 bufs x 32KB @131072, ssred @229376 (2KB)
#define SM_B 0
#define SM_A 131072
#define SM_SS 229376
#define SMEMSZ 231424

// ---------------- fused setup: bucketed CSR + x->bf16 hi/lo + weight prep ----------------
struct WPtrs { const float* Wl[5]; const float* Wr[5]; };
#define CB 7032
#define XB 6250
#define WB 320
__global__ __launch_bounds__(256) void setup_kernel(const int* __restrict__ e0,
                                                    const int* __restrict__ e1,
                                                    const int* __restrict__ e2,
                                                    WPtrs wp,
                                                    const float* __restrict__ x,
                                                    __nv_bfloat16* __restrict__ oh,
                                                    __nv_bfloat16* __restrict__ ol,
                                                    __nv_bfloat16* __restrict__ wtb,
                                                    int* __restrict__ deg,
                                                    int* __restrict__ csr) {
    int b = blockIdx.x, tid = threadIdx.x;
    if (b < CB) {
        int t = b * 256 + tid;
        if (t < 3 * EE) {
            int s = t / EE, i = t - s * EE;
            const int* e = (s == 0) ? e0 : ((s == 1) ? e1 : e2);
            int dst = e[EE + i];
            int p = atomicAdd(&deg[s * NN + dst], 1);
            if (p < DCAP) csr[((size_t)s * NN + dst) * DCAP + p] = e[i];
        }
    } else if (b < CB + XB) {
        int i = (b - CB) * 256 + tid;
        float4 v = ((const float4*)x)[i];
        __nv_bfloat162 h01, h23, l01, l23;
        h01.x = __float2bfloat16(v.x); l01.x = __float2bfloat16(v.x - __bfloat162float(h01.x));
        h01.y = __float2bfloat16(v.y); l01.y = __float2bfloat16(v.y - __bfloat162float(h01.y));
        h23.x = __float2bfloat16(v.z); l23.x = __float2bfloat16(v.z - __bfloat162float(h23.x));
        h23.y = __float2bfloat16(v.w); l23.y = __float2bfloat16(v.w - __bfloat162float(h23.y));
        ((__nv_bfloat162*)oh)[i * 2] = h01; ((__nv_bfloat162*)oh)[i * 2 + 1] = h23;
        ((__nv_bfloat162*)ol)[i * 2] = l01; ((__nv_bfloat162*)ol)[i * 2 + 1] = l23;
    } else if (b < CB + XB + WB) {
        int idx = (b - CB - XB) * 256 + tid;
        int cv = idx >> 14, rem = idx & 16383;
        int n = rem >> 7, k = rem & 127;
        __nv_bfloat16* base = wtb + (size_t)cv * 4 * HH * HH;
        float a = wp.Wl[cv][k * HH + n];
        __nv_bfloat16 ah = __float2bfloat16(a);
        base[n * HH + k] = ah;
        base[HH * HH + n * HH + k] = __float2bfloat16(a - __bfloat162float(ah));
        float w = wp.Wr[cv][k * HH + n];
        __nv_bfloat16 bh = __float2bfloat16(w);
        base[2 * HH * HH + n * HH + k] = bh;
        base[3 * HH * HH + n * HH + k] = __float2bfloat16(w - __bfloat162float(bh));
    }
}

// ---------------- pool zero (keeps sage_mma at launch #4 for ncu) ----------------
__global__ void zpool_kernel(float* __restrict__ poolp) {
    poolp[blockIdx.x * 256 + threadIdx.x] = 0.f;
}

// ---------------- mean aggregation (lanes 0-15 hi, 16-31 lo) ----------------
__global__ __launch_bounds__(256) void agg_kernel(const __nv_bfloat16* __restrict__ hH,
                                                  const __nv_bfloat16* __restrict__ hL,
                                                  __nv_bfloat16* __restrict__ aggH,
                                                  __nv_bfloat16* __restrict__ aggL,
                                                  const int* __restrict__ csr,
                                                  const int* __restrict__ deg) {
    int node = blockIdx.x * 8 + (threadIdx.x >> 5);
    if (node >= NN) return;
    int lane = threadIdx.x & 31;
    int half = lane >> 4;
    int co = (lane & 15) * 8;
    const __nv_bfloat16* src = half ? hL : hH;
    int d = deg[node];
    int dr = min(d, DCAP);
    const int* nb = csr + (size_t)node * DCAP;
    float acc[8];
#pragma unroll
    for (int r = 0; r < 8; r++) acc[r] = 0.f;

    auto addv = [&](uint4 v) {
        __nv_bfloat162* bp = (__nv_bfloat162*)&v;
#pragma unroll
        for (int q = 0; q < 4; q++) {
            float2 f = __bfloat1622float2(bp[q]);
            acc[2 * q] += f.x;
            acc[2 * q + 1] += f.y;
        }
    };

    int p = 0;
    for (; p + 4 <= dr; p += 4) {
        int4 iv = *(const int4*)(nb + p);
        uint4 v0 = *(const uint4*)(src + (size_t)iv.x * HH + co);
        uint4 v1 = *(const uint4*)(src + (size_t)iv.y * HH + co);
        uint4 v2 = *(const uint4*)(src + (size_t)iv.z * HH + co);
        uint4 v3 = *(const uint4*)(src + (size_t)iv.w * HH + co);
        addv(v0); addv(v1); addv(v2); addv(v3);
    }
    for (; p < dr; ++p) {
        uint4 v0 = *(const uint4*)(src + (size_t)nb[p] * HH + co);
        addv(v0);
    }
    float inv = 1.f / fmaxf((float)d, 1.f);
#pragma unroll
    for (int r = 0; r < 8; r++) {
        acc[r] *= inv;
        acc[r] += __shfl_xor_sync(0xffffffffu, acc[r], 16);
    }
    __nv_bfloat16 hv[8];
#pragma unroll
    for (int r = 0; r < 8; r++) hv[r] = __float2bfloat16(acc[r]);
    if (half == 0) {
        *(uint4*)(aggH + (size_t)node * HH + co) = *(uint4*)hv;
    } else {
        __nv_bfloat16 lv[8];
#pragma unroll
        for (int r = 0; r < 8; r++)
            lv[r] = __float2bfloat16(acc[r] - __bfloat162float(hv[r]));
        *(uint4*)(aggL + (size_t)node * HH + co) = *(uint4*)lv;
    }
}

// ---------------- persistent bf16-split tensor-core SAGE GEMM, 512 threads ----------------
// grid = 148, 16 warps (4/SMSP) for latency hiding; warp tile 32x32 over BM=128.
__global__ __launch_bounds__(512) void sage_mma(const __nv_bfloat16* __restrict__ aggH,
                                                const __nv_bfloat16* __restrict__ aggL,
                                                const __nv_bfloat16* __restrict__ hinH,
                                                const __nv_bfloat16* __restrict__ hinL,
                                                const __nv_bfloat16* __restrict__ wb,
                                                const float* __restrict__ bias,
                                                float* __restrict__ outF,
                                                __nv_bfloat16* __restrict__ outH,
                                                __nv_bfloat16* __restrict__ outL,
                                                int doNorm, int writeF) {
    extern __shared__ char smem[];
    const uint32_t sb = s2u(smem);
    const int tid = threadIdx.x;
    const int wid = tid >> 5, lane = tid & 31;
    const int wm = wid >> 2, wn = wid & 3;    // wm 0..3 (32-row group), wn 0..3 (32-col group)
    const int bid = blockIdx.x;
    const int nch = 4 * ((NTILES - bid + 147) / 148);

    // B load: 4 matrices x 32KB, swizzled [n][256B rows]
#pragma unroll
    for (int i = 0; i < 16; i++) {
        int idx = tid + i * 512;
        int a = idx >> 11, u = idx & 2047;
        int n = u >> 4, kunit = u & 15;
        uint32_t off = (uint32_t)(n * 256 + kunit * 16);
        uint32_t sw = off ^ ((off >> 4) & 0x70);
        cpa16(sb + SM_B + a * 32768 + sw, wb + (size_t)idx * 8, 16u);
    }
    auto issueA = [&](int ch) {
        int tile = bid + (ch >> 2) * 148;
        int c = ch & 3, buf = ch % 3;
        int m0 = tile * 128;
        const __nv_bfloat16* sH = (c < 2) ? aggH : hinH;
        const __nv_bfloat16* sL = (c < 2) ? aggL : hinL;
        int koff = (c & 1) * 64;
#pragma unroll
        for (int i = 0; i < 2; i++) {
            int idx = tid + i * 512;
            int r = idx >> 3, ku = idx & 7;
            int gm = m0 + r;
            uint32_t off = (uint32_t)(r * 128 + ku * 16);
            uint32_t sw = off ^ ((off >> 3) & 0x70);
            uint32_t ssz = (gm < NN) ? 16u : 0u;
            int gmc = (gm < NN) ? gm : 0;
            cpa16(sb + SM_A + buf * 32768 + sw,         sH + (size_t)gmc * HH + koff + ku * 8, ssz);
            cpa16(sb + SM_A + buf * 32768 + 16384 + sw, sL + (size_t)gmc * HH + koff + ku * 8, ssz);
        }
    };
    issueA(0); cpa_commit();
    issueA(1); cpa_commit();

    float acc[2][4][4];
#pragma unroll
    for (int mf = 0; mf < 2; mf++)
#pragma unroll
        for (int nf = 0; nf < 4; nf++)
#pragma unroll
            for (int q = 0; q < 4; q++) acc[mf][nf][q] = 0.f;

    float* ssred = (float*)(smem + SM_SS);
    float bc[4][2];
#pragma unroll
    for (int nf = 0; nf < 4; nf++) {
        int col = wn * 32 + nf * 8 + (lane & 3) * 2;
        bc[nf][0] = __ldg(bias + col);
        bc[nf][1] = __ldg(bias + col + 1);
    }

    const uint32_t rAl = (uint32_t)(wm * 32 + (lane & 15));
    const uint32_t kAl = (uint32_t)((lane >> 4) * 16);
    const uint32_t nBl = (uint32_t)(wn * 32 + ((lane >> 4) << 3) + (lane & 7));
    const uint32_t kBl = (uint32_t)(((lane >> 3) & 1) * 16);

    for (int ch = 0; ch < nch; ch++) {
        if (ch + 2 < nch) cpa_wait<1>(); else cpa_wait<0>();
        __syncthreads();
        if (ch + 2 < nch) { issueA(ch + 2); cpa_commit(); }

        const int buf = ch % 3, c = ch & 3, ph = c >> 1;
        const uint32_t Ah = sb + SM_A + buf * 32768;
        const uint32_t Al = Ah + 16384;
        const uint32_t Bh = sb + SM_B + (ph * 2 + 0) * 32768;
        const uint32_t Bl = sb + SM_B + (ph * 2 + 1) * 32768;
        const uint32_t kbB0 = (uint32_t)((c & 1) * 128);
#pragma unroll
        for (int kc = 0; kc < 4; kc++) {
            uint32_t kbA = kc * 32 + kAl;
            uint32_t kbB = kbB0 + kc * 32 + kBl;
            uint32_t ah[2][4], al[2][4];
#pragma unroll
            for (int mf = 0; mf < 2; mf++) {
                uint32_t off = (rAl + mf * 16) * 128 + kbA;
                uint32_t sw = off ^ ((off >> 3) & 0x70);
                LDSM4(ah[mf][0], ah[mf][1], ah[mf][2], ah[mf][3], Ah + sw);
                LDSM4(al[mf][0], al[mf][1], al[mf][2], al[mf][3], Al + sw);
            }
            uint32_t bh[4][2], bl[4][2];
#pragma unroll
            for (int np = 0; np < 2; np++) {
                uint32_t off = (nBl + np * 16) * 256 + kbB;
                uint32_t sw = off ^ ((off >> 4) & 0x70);
                uint32_t r0, r1, r2, r3;
                LDSM4(r0, r1, r2, r3, Bh + sw);
                bh[2 * np][0] = r0; bh[2 * np][1] = r1;
                bh[2 * np + 1][0] = r2; bh[2 * np + 1][1] = r3;
                LDSM4(r0, r1, r2, r3, Bl + sw);
                bl[2 * np][0] = r0; bl[2 * np][1] = r1;
                bl[2 * np + 1][0] = r2; bl[2 * np + 1][1] = r3;
            }
#pragma unroll
            for (int mf = 0; mf < 2; mf++)
#pragma unroll
                for (int nf = 0; nf < 4; nf++) {
                    MMA_BF16(acc[mf][nf], ah[mf], bh[nf]);
                    MMA_BF16(acc[mf][nf], ah[mf], bl[nf]);
                    MMA_BF16(acc[mf][nf], al[mf], bh[nf]);
                }
        }

        if ((ch & 3) == 3) {
            // ---------------- epilogue for this tile ----------------
            int m0 = (bid + (ch >> 2) * 148) * 128;
#pragma unroll
            for (int mf = 0; mf < 2; mf++)
#pragma unroll
                for (int nf = 0; nf < 4; nf++) {
                    acc[mf][nf][0] += bc[nf][0];
                    acc[mf][nf][1] += bc[nf][1];
                    acc[mf][nf][2] += bc[nf][0];
                    acc[mf][nf][3] += bc[nf][1];
                }
            float scale[2][2];
            if (doNorm) {
#pragma unroll
                for (int mf = 0; mf < 2; mf++) {
                    float s0 = 0.f, s1 = 0.f;
#pragma unroll
                    for (int nf = 0; nf < 4; nf++) {
                        s0 += acc[mf][nf][0] * acc[mf][nf][0] + acc[mf][nf][1] * acc[mf][nf][1];
                        s1 += acc[mf][nf][2] * acc[mf][nf][2] + acc[mf][nf][3] * acc[mf][nf][3];
                    }
                    s0 += __shfl_xor_sync(0xffffffffu, s0, 1);
                    s0 += __shfl_xor_sync(0xffffffffu, s0, 2);
                    s1 += __shfl_xor_sync(0xffffffffu, s1, 1);
                    s1 += __shfl_xor_sync(0xffffffffu, s1, 2);
                    if ((lane & 3) == 0) {
                        int r = wm * 32 + mf * 16 + (lane >> 2);
                        ssred[r * 4 + wn] = s0;
                        ssred[(r + 8) * 4 + wn] = s1;
                    }
                }
                __syncthreads();
#pragma unroll
                for (int mf = 0; mf < 2; mf++) {
                    int r = wm * 32 + mf * 16 + (lane >> 2);
                    float t0 = ssred[r * 4] + ssred[r * 4 + 1] + ssred[r * 4 + 2] + ssred[r * 4 + 3];
                    int r1 = r + 8;
                    float t1 = ssred[r1 * 4] + ssred[r1 * 4 + 1] + ssred[r1 * 4 + 2] + ssred[r1 * 4 + 3];
                    scale[mf][0] = 1.f / fmaxf(sqrtf(t0), 1e-12f);
                    scale[mf][1] = 1.f / fmaxf(sqrtf(t1), 1e-12f);
                }
            } else {
#pragma unroll
                for (int mf = 0; mf < 2; mf++) { scale[mf][0] = 1.f; scale[mf][1] = 1.f; }
            }
#pragma unroll
            for (int mf = 0; mf < 2; mf++)
#pragma unroll
                for (int hh = 0; hh < 2; hh++) {
                    int r = m0 + wm * 32 + mf * 16 + (lane >> 2) + hh * 8;
                    if (r < NN) {
#pragma unroll
                        for (int nf = 0; nf < 4; nf++) {
                            int col = wn * 32 + nf * 8 + (lane & 3) * 2;
                            float v0 = acc[mf][nf][2 * hh] * scale[mf][hh];
                            float v1 = acc[mf][nf][2 * hh + 1] * scale[mf][hh];
                            if (writeF) {
                                *(float2*)(outF + (size_t)r * HH + col) = make_float2(v0, v1);
                            }
                            __nv_bfloat162 hv, lv;
                            hv.x = __float2bfloat16(v0);
                            hv.y = __float2bfloat16(v1);
                            lv.x = __float2bfloat16(v0 - __bfloat162float(hv.x));
                            lv.y = __float2bfloat16(v1 - __bfloat162float(hv.y));
                            *(__nv_bfloat162*)(outH + (size_t)r * HH + col) = hv;
                            *(__nv_bfloat162*)(outL + (size_t)r * HH + col) = lv;
                        }
                    }
                }
#pragma unroll
            for (int mf = 0; mf < 2; mf++)
#pragma unroll
                for (int nf = 0; nf < 4; nf++)
#pragma unroll
                    for (int q = 0; q < 4; q++) acc[mf][nf][q] = 0.f;
        }
    }
}

// ---------------- global_add_pool (+ re-zero deg for next replay) ----------------
__global__ __launch_bounds__(128) void pool_kernel(const float* __restrict__ h,
                                                   const int* __restrict__ batch,
                                                   float* __restrict__ pool,
                                                   int* __restrict__ deg) {
    int gtid = blockIdx.x * 128 + threadIdx.x;
    for (int i = gtid; i < 3 * NN; i += gridDim.x * 128) deg[i] = 0;
    int c = threadIdx.x;
    int start = blockIdx.x * PCH;
    if (start >= NN) return;
    int end = min(start + PCH, NN);
    int cur = batch[start];
    float acc = 0.f;
    for (int i = start; i < end; ++i) {
        int b = batch[i];
        if (b != cur) { atomicAdd(&pool[cur * HH + c], acc); acc = 0.f; cur = b; }
        acc += h[(size_t)i * HH + c];
    }
    atomicAdd(&pool[cur * HH + c], acc);
}

// ---------------- MLP head ----------------
__global__ __launch_bounds__(256) void mlp_kernel(const float* __restrict__ pool,
                                                  const float* __restrict__ W0, const float* __restrict__ b0,
                                                  const float* __restrict__ W1, const float* __restrict__ b1,
                                                  const float* __restrict__ hW, const float* __restrict__ hb,
                                                  float* __restrict__ out) {
    __shared__ float Gs[GG * HH];
    int tid = threadIdx.x;
    for (int i = tid; i < GG * HH / 4; i += 256)
        ((float4*)Gs)[i] = ((const float4*)pool)[i];
    __syncthreads();
    int c = tid & 127;
    int rb = tid >> 7;
    float s[32];
#pragma unroll
    for (int j = 0; j < 32; j++) s[j] = b0[c];
    for (int k = 0; k < HH; k++) {
        float w = __ldg(W0 + k * HH + c);
#pragma unroll
        for (int j = 0; j < 32; j++) s[j] = fmaf(Gs[(rb + 2 * j) * HH + k], w, s[j]);
    }
    __syncthreads();
#pragma unroll
    for (int j = 0; j < 32; j++) Gs[(rb + 2 * j) * HH + c] = fmaxf(s[j], 0.f);
    __syncthreads();
#pragma unroll
    for (int j = 0; j < 32; j++) s[j] = b1[c];
    for (int k = 0; k < HH; k++) {
        float w = __ldg(W1 + k * HH + c);
#pragma unroll
        for (int j = 0; j < 32; j++) s[j] = fmaf(Gs[(rb + 2 * j) * HH + k], w, s[j]);
    }
    __syncthreads();
#pragma unroll
    for (int j = 0; j < 32; j++) Gs[(rb + 2 * j) * HH + c] = fmaxf(s[j], 0.f);
    __syncthreads();
    if (tid < GG) {
        float acc = hb[0];
        for (int k = 0; k < HH; k++) acc = fmaf(Gs[tid * HH + k], hW[k], acc);
        out[tid] = acc;
    }
}

// ---------------- driver ----------------
extern "C" void kernel_launch(void* const* d_in, const int* in_sizes, int n_in,
                              void* d_out, int out_size) {
    const float* x     = (const float*)d_in[0];
    const int*   eic   = (const int*)d_in[1];
    const int*   eid   = (const int*)d_in[2];
    const int*   eit   = (const int*)d_in[3];
    const int*   batch = (const int*)d_in[4];
    WPtrs wp;
    const float* bl[5];
    for (int i = 0; i < 5; i++) {
        wp.Wl[i] = (const float*)d_in[5 + 3 * i];
        bl[i]    = (const float*)d_in[6 + 3 * i];
        wp.Wr[i] = (const float*)d_in[7 + 3 * i];
    }
    const float* l0W   = (const float*)d_in[20];
    const float* l0b   = (const float*)d_in[21];
    const float* l1W   = (const float*)d_in[22];
    const float* l1b   = (const float*)d_in[23];
    const float* headW = (const float*)d_in[24];
    const float* headb = (const float*)d_in[25];

    void* p;
    cudaGetSymbolAddress(&p, g_bufA); float* bufA = (float*)p;
    cudaGetSymbolAddress(&p, g_pool); float* poolp = (float*)p;
    cudaGetSymbolAddress(&p, g_deg);  int* degp = (int*)p;
    cudaGetSymbolAddress(&p, g_csr);  int* csrp = (int*)p;
    cudaGetSymbolAddress(&p, g_hH);   __nv_bfloat16* hH = (__nv_bfloat16*)p;
    cudaGetSymbolAddress(&p, g_hL);   __nv_bfloat16* hL = (__nv_bfloat16*)p;
    cudaGetSymbolAddress(&p, g_aggH); __nv_bfloat16* aggH = (__nv_bfloat16*)p;
    cudaGetSymbolAddress(&p, g_aggL); __nv_bfloat16* aggL = (__nv_bfloat16*)p;
    cudaGetSymbolAddress(&p, g_wtb);  __nv_bfloat16* wtb = (__nv_bfloat16*)p;

    cudaFuncSetAttribute(sage_mma, cudaFuncAttributeMaxDynamicSharedMemorySize, SMEMSZ);

    size_t bufsz = (size_t)NN * HH;
    setup_kernel<<<CB + XB + WB, 256>>>(eid, eic, eit, wp, x,
                                        hH + bufsz, hL + bufsz, wtb, degp, csrp);  // 1
    zpool_kernel<<<GG * HH / 256, 256>>>(poolp);                                   // 2

    const int Les[7] = {0, 1, 1, 2, 0, 1, 1};
    const int Lcv[7] = {0, 1, 1, 2, 3, 4, 4};
    const int Lnm[7] = {1, 1, 1, 0, 1, 1, 1};

    for (int li = 0; li < 7; ++li) {
        int es = Les[li], cv = Lcv[li];
        int in = (li + 1) & 1, outi = li & 1;
        agg_kernel<<<(NN + 7) / 8, 256>>>(hH + (size_t)in * bufsz, hL + (size_t)in * bufsz,
                                          aggH, aggL,
                                          csrp + (size_t)es * NN * DCAP, degp + es * NN);
        sage_mma<<<148, 512, SMEMSZ>>>(
            aggH, aggL, hH + (size_t)in * bufsz, hL + (size_t)in * bufsz,
            wtb + (size_t)cv * 4 * HH * HH, bl[cv],
            bufA, hH + (size_t)outi * bufsz, hL + (size_t)outi * bufsz,
            Lnm[li], li == 6 ? 1 : 0);
    }

    pool_kernel<<<(NN + PCH - 1) / PCH, 128>>>(bufA, batch, poolp, degp);
    mlp_kernel<<<1, 256>>>(poolp, l0W, l0b, l1W, l1b, headW, headb, (float*)d_out);
}

// round 11
// speedup vs baseline: 1.0188x; 1.0188x over previous
#include <cuda_runtime.h>
#include <cuda_bf16.h>
#include <math.h>
#include <stdint.h>

#define NN 50000
#define EE 600000
#define HH 128
#define GG 64
#define PCH 64
#define DCAP 64
#define NTILES 391   // ceil(50000/128)

// ---- static device scratch ----
__device__ float g_bufA[(size_t)NN * HH];
__device__ float g_pool[GG * HH];
__device__ int   g_deg[3 * NN];                 // zeroed at load; re-zeroed by pool_kernel
__device__ int   g_csr[(size_t)3 * NN * DCAP];
__device__ __nv_bfloat16 g_hH[2][(size_t)NN * HH];
__device__ __nv_bfloat16 g_hL[2][(size_t)NN * HH];
__device__ __nv_bfloat16 g_aggH[(size_t)NN * HH];
__device__ __nv_bfloat16 g_aggL[(size_t)NN * HH];
// weights bf16: [conv 5][phase 2][hi/lo 2][n=128][k=128]
__device__ __nv_bfloat16 g_wtb[5 * 4 * HH * HH];

// ================= helpers =================
__device__ __forceinline__ uint32_t s2u(const void* p) {
    uint32_t a;
    asm("{ .reg .u64 t; cvta.to.shared.u64 t, %1; cvt.u32.u64 %0, t; }" : "=r"(a) : "l"(p));
    return a;
}
__device__ __forceinline__ void cpa16(uint32_t d, const void* s, uint32_t ssz) {
    asm volatile("cp.async.cg.shared.global [%0], [%1], 16, %2;"
                 :: "r"(d), "l"(s), "r"(ssz) : "memory");
}
__device__ __forceinline__ void cpa_commit() {
    asm volatile("cp.async.commit_group;" ::: "memory");
}
template <int N>
__device__ __forceinline__ void cpa_wait() {
    asm volatile("cp.async.wait_group %0;" :: "n"(N) : "memory");
}
#define LDSM4(r0, r1, r2, r3, a) \
    asm volatile("ldmatrix.sync.aligned.m8n8.x4.shared.b16 {%0,%1,%2,%3}, [%4];" \
                 : "=r"(r0), "=r"(r1), "=r"(r2), "=r"(r3) : "r"(a))
#define MMA_BF16(c, a, b) \
    asm volatile("mma.sync.aligned.m16n8k16.row.col.f32.bf16.bf16.f32 " \
                 "{%0,%1,%2,%3},{%4,%5,%6,%7},{%8,%9},{%0,%1,%2,%3};" \
                 : "+f"((c)[0]), "+f"((c)[1]), "+f"((c)[2]), "+f"((c)[3]) \
                 : "r"((a)[0]), "r"((a)[1]), "r"((a)[2]), "r"((a)[3]), \
                   "r"((b)[0]), "r"((b)[1]))

// smem: B 4x32KB @0, A 3 bufs x 32KB @131072, ssred @229376 (2KB)
#define SM_B 0
#define SM_A 131072
#define SM_SS 229376
#define SMEMSZ 231424

// ---------------- fused setup: bucketed CSR + x->bf16 hi/lo + weight prep ----------------
struct WPtrs { const float* Wl[5]; const float* Wr[5]; };
#define CB 7032
#define XB 6250
#define WB 320
__global__ __launch_bounds__(256) void setup_kernel(const int* __restrict__ e0,
                                                    const int* __restrict__ e1,
                                                    const int* __restrict__ e2,
                                                    WPtrs wp,
                                                    const float* __restrict__ x,
                                                    __nv_bfloat16* __restrict__ oh,
                                                    __nv_bfloat16* __restrict__ ol,
                                                    __nv_bfloat16* __restrict__ wtb,
                                                    int* __restrict__ deg,
                                                    int* __restrict__ csr) {
    int b = blockIdx.x, tid = threadIdx.x;
    if (b < CB) {
        int t = b * 256 + tid;
        if (t < 3 * EE) {
            int s = t / EE, i = t - s * EE;
            const int* e = (s == 0) ? e0 : ((s == 1) ? e1 : e2);
            int dst = e[EE + i];
            int p = atomicAdd(&deg[s * NN + dst], 1);
            if (p < DCAP) csr[((size_t)s * NN + dst) * DCAP + p] = e[i];
        }
    } else if (b < CB + XB) {
        int i = (b - CB) * 256 + tid;
        float4 v = ((const float4*)x)[i];
        __nv_bfloat162 h01, h23, l01, l23;
        h01.x = __float2bfloat16(v.x); l01.x = __float2bfloat16(v.x - __bfloat162float(h01.x));
        h01.y = __float2bfloat16(v.y); l01.y = __float2bfloat16(v.y - __bfloat162float(h01.y));
        h23.x = __float2bfloat16(v.z); l23.x = __float2bfloat16(v.z - __bfloat162float(h23.x));
        h23.y = __float2bfloat16(v.w); l23.y = __float2bfloat16(v.w - __bfloat162float(h23.y));
        ((__nv_bfloat162*)oh)[i * 2] = h01; ((__nv_bfloat162*)oh)[i * 2 + 1] = h23;
        ((__nv_bfloat162*)ol)[i * 2] = l01; ((__nv_bfloat162*)ol)[i * 2 + 1] = l23;
    } else if (b < CB + XB + WB) {
        int idx = (b - CB - XB) * 256 + tid;
        int cv = idx >> 14, rem = idx & 16383;
        int n = rem >> 7, k = rem & 127;
        __nv_bfloat16* base = wtb + (size_t)cv * 4 * HH * HH;
        float a = wp.Wl[cv][k * HH + n];
        __nv_bfloat16 ah = __float2bfloat16(a);
        base[n * HH + k] = ah;
        base[HH * HH + n * HH + k] = __float2bfloat16(a - __bfloat162float(ah));
        float w = wp.Wr[cv][k * HH + n];
        __nv_bfloat16 bh = __float2bfloat16(w);
        base[2 * HH * HH + n * HH + k] = bh;
        base[3 * HH * HH + n * HH + k] = __float2bfloat16(w - __bfloat162float(bh));
    }
}

// ---------------- pool zero (keeps sage_mma at launch #4 for ncu) ----------------
__global__ void zpool_kernel(float* __restrict__ poolp) {
    poolp[blockIdx.x * 256 + threadIdx.x] = 0.f;
}

// ---------------- mean aggregation (lanes 0-15 hi, 16-31 lo) ----------------
__global__ __launch_bounds__(256) void agg_kernel(const __nv_bfloat16* __restrict__ hH,
                                                  const __nv_bfloat16* __restrict__ hL,
                                                  __nv_bfloat16* __restrict__ aggH,
                                                  __nv_bfloat16* __restrict__ aggL,
                                                  const int* __restrict__ csr,
                                                  const int* __restrict__ deg) {
    int node = blockIdx.x * 8 + (threadIdx.x >> 5);
    if (node >= NN) return;
    int lane = threadIdx.x & 31;
    int half = lane >> 4;
    int co = (lane & 15) * 8;
    const __nv_bfloat16* src = half ? hL : hH;
    int d = deg[node];
    int dr = min(d, DCAP);
    const int* nb = csr + (size_t)node * DCAP;
    float acc[8];
#pragma unroll
    for (int r = 0; r < 8; r++) acc[r] = 0.f;

    auto addv = [&](uint4 v) {
        __nv_bfloat162* bp = (__nv_bfloat162*)&v;
#pragma unroll
        for (int q = 0; q < 4; q++) {
            float2 f = __bfloat1622float2(bp[q]);
            acc[2 * q] += f.x;
            acc[2 * q + 1] += f.y;
        }
    };

    int p = 0;
    for (; p + 4 <= dr; p += 4) {
        int4 iv = *(const int4*)(nb + p);
        uint4 v0 = *(const uint4*)(src + (size_t)iv.x * HH + co);
        uint4 v1 = *(const uint4*)(src + (size_t)iv.y * HH + co);
        uint4 v2 = *(const uint4*)(src + (size_t)iv.z * HH + co);
        uint4 v3 = *(const uint4*)(src + (size_t)iv.w * HH + co);
        addv(v0); addv(v1); addv(v2); addv(v3);
    }
    for (; p < dr; ++p) {
        uint4 v0 = *(const uint4*)(src + (size_t)nb[p] * HH + co);
        addv(v0);
    }
    float inv = 1.f / fmaxf((float)d, 1.f);
#pragma unroll
    for (int r = 0; r < 8; r++) {
        acc[r] *= inv;
        acc[r] += __shfl_xor_sync(0xffffffffu, acc[r], 16);
    }
    __nv_bfloat16 hv[8];
#pragma unroll
    for (int r = 0; r < 8; r++) hv[r] = __float2bfloat16(acc[r]);
    if (half == 0) {
        *(uint4*)(aggH + (size_t)node * HH + co) = *(uint4*)hv;
    } else {
        __nv_bfloat16 lv[8];
#pragma unroll
        for (int r = 0; r < 8; r++)
            lv[r] = __float2bfloat16(acc[r] - __bfloat162float(hv[r]));
        *(uint4*)(aggL + (size_t)node * HH + co) = *(uint4*)lv;
    }
}

// ---------------- persistent bf16-split tensor-core SAGE GEMM, 512 threads ----------------
// Register-level fragment double-buffering: kc+1's LDSMs issue before kc's MMAs,
// so LDSM latency hides under the HMMA stream and the tensor pipe stays fed.
__global__ __launch_bounds__(512) void sage_mma(const __nv_bfloat16* __restrict__ aggH,
                                                const __nv_bfloat16* __restrict__ aggL,
                                                const __nv_bfloat16* __restrict__ hinH,
                                                const __nv_bfloat16* __restrict__ hinL,
                                                const __nv_bfloat16* __restrict__ wb,
                                                const float* __restrict__ bias,
                                                float* __restrict__ outF,
                                                __nv_bfloat16* __restrict__ outH,
                                                __nv_bfloat16* __restrict__ outL,
                                                int doNorm, int writeF) {
    extern __shared__ char smem[];
    const uint32_t sb = s2u(smem);
    const int tid = threadIdx.x;
    const int wid = tid >> 5, lane = tid & 31;
    const int wm = wid >> 2, wn = wid & 3;
    const int bid = blockIdx.x;
    const int nch = 4 * ((NTILES - bid + 147) / 148);

    // B load: 4 matrices x 32KB, swizzled [n][256B rows]
#pragma unroll
    for (int i = 0; i < 16; i++) {
        int idx = tid + i * 512;
        int a = idx >> 11, u = idx & 2047;
        int n = u >> 4, kunit = u & 15;
        uint32_t off = (uint32_t)(n * 256 + kunit * 16);
        uint32_t sw = off ^ ((off >> 4) & 0x70);
        cpa16(sb + SM_B + a * 32768 + sw, wb + (size_t)idx * 8, 16u);
    }
    auto issueA = [&](int ch) {
        int tile = bid + (ch >> 2) * 148;
        int c = ch & 3, buf = ch % 3;
        int m0 = tile * 128;
        const __nv_bfloat16* sH = (c < 2) ? aggH : hinH;
        const __nv_bfloat16* sL = (c < 2) ? aggL : hinL;
        int koff = (c & 1) * 64;
#pragma unroll
        for (int i = 0; i < 2; i++) {
            int idx = tid + i * 512;
            int r = idx >> 3, ku = idx & 7;
            int gm = m0 + r;
            uint32_t off = (uint32_t)(r * 128 + ku * 16);
            uint32_t sw = off ^ ((off >> 3) & 0x70);
            uint32_t ssz = (gm < NN) ? 16u : 0u;
            int gmc = (gm < NN) ? gm : 0;
            cpa16(sb + SM_A + buf * 32768 + sw,         sH + (size_t)gmc * HH + koff + ku * 8, ssz);
            cpa16(sb + SM_A + buf * 32768 + 16384 + sw, sL + (size_t)gmc * HH + koff + ku * 8, ssz);
        }
    };
    issueA(0); cpa_commit();
    issueA(1); cpa_commit();

    float acc[2][4][4];
#pragma unroll
    for (int mf = 0; mf < 2; mf++)
#pragma unroll
        for (int nf = 0; nf < 4; nf++)
#pragma unroll
            for (int q = 0; q < 4; q++) acc[mf][nf][q] = 0.f;

    float* ssred = (float*)(smem + SM_SS);
    float bc[4][2];
#pragma unroll
    for (int nf = 0; nf < 4; nf++) {
        int col = wn * 32 + nf * 8 + (lane & 3) * 2;
        bc[nf][0] = __ldg(bias + col);
        bc[nf][1] = __ldg(bias + col + 1);
    }

    const uint32_t rAl = (uint32_t)(wm * 32 + (lane & 15));
    const uint32_t kAl = (uint32_t)((lane >> 4) * 16);
    const uint32_t nBl = (uint32_t)(wn * 32 + ((lane >> 4) << 3) + (lane & 7));
    const uint32_t kBl = (uint32_t)(((lane >> 3) & 1) * 16);

    // double-buffered register fragments
    uint32_t ah[2][2][4], al[2][2][4], bh[2][4][2], bl[2][4][2];

    for (int ch = 0; ch < nch; ch++) {
        if (ch + 2 < nch) cpa_wait<1>(); else cpa_wait<0>();
        __syncthreads();
        if (ch + 2 < nch) { issueA(ch + 2); cpa_commit(); }

        const int buf = ch % 3, c = ch & 3, ph = c >> 1;
        const uint32_t Ah = sb + SM_A + buf * 32768;
        const uint32_t Al = Ah + 16384;
        const uint32_t Bh = sb + SM_B + (ph * 2 + 0) * 32768;
        const uint32_t Bl = sb + SM_B + (ph * 2 + 1) * 32768;
        const uint32_t kbB0 = (uint32_t)((c & 1) * 128);

        // fragment loader for step kc into register-buffer fb
        auto ldfr = [&](int kc, int fb) {
            uint32_t kbA = kc * 32 + kAl;
            uint32_t kbB = kbB0 + kc * 32 + kBl;
#pragma unroll
            for (int mf = 0; mf < 2; mf++) {
                uint32_t off = (rAl + mf * 16) * 128 + kbA;
                uint32_t sw = off ^ ((off >> 3) & 0x70);
                LDSM4(ah[fb][mf][0], ah[fb][mf][1], ah[fb][mf][2], ah[fb][mf][3], Ah + sw);
                LDSM4(al[fb][mf][0], al[fb][mf][1], al[fb][mf][2], al[fb][mf][3], Al + sw);
            }
#pragma unroll
            for (int np = 0; np < 2; np++) {
                uint32_t off = (nBl + np * 16) * 256 + kbB;
                uint32_t sw = off ^ ((off >> 4) & 0x70);
                uint32_t r0, r1, r2, r3;
                LDSM4(r0, r1, r2, r3, Bh + sw);
                bh[fb][2 * np][0] = r0; bh[fb][2 * np][1] = r1;
                bh[fb][2 * np + 1][0] = r2; bh[fb][2 * np + 1][1] = r3;
                LDSM4(r0, r1, r2, r3, Bl + sw);
                bl[fb][2 * np][0] = r0; bl[fb][2 * np][1] = r1;
                bl[fb][2 * np + 1][0] = r2; bl[fb][2 * np + 1][1] = r3;
            }
        };

        ldfr(0, 0);
#pragma unroll
        for (int kc = 0; kc < 4; kc++) {
            const int fb = kc & 1;
            if (kc < 3) ldfr(kc + 1, fb ^ 1);   // prefetch next step's fragments
#pragma unroll
            for (int mf = 0; mf < 2; mf++)
#pragma unroll
                for (int nf = 0; nf < 4; nf++) {
                    MMA_BF16(acc[mf][nf], ah[fb][mf], bh[fb][nf]);
                    MMA_BF16(acc[mf][nf], ah[fb][mf], bl[fb][nf]);
                    MMA_BF16(acc[mf][nf], al[fb][mf], bh[fb][nf]);
                }
        }

        if ((ch & 3) == 3) {
            // ---------------- epilogue for this tile ----------------
            int m0 = (bid + (ch >> 2) * 148) * 128;
#pragma unroll
            for (int mf = 0; mf < 2; mf++)
#pragma unroll
                for (int nf = 0; nf < 4; nf++) {
                    acc[mf][nf][0] += bc[nf][0];
                    acc[mf][nf][1] += bc[nf][1];
                    acc[mf][nf][2] += bc[nf][0];
                    acc[mf][nf][3] += bc[nf][1];
                }
            float scale[2][2];
            if (doNorm) {
#pragma unroll
                for (int mf = 0; mf < 2; mf++) {
                    float s0 = 0.f, s1 = 0.f;
#pragma unroll
                    for (int nf = 0; nf < 4; nf++) {
                        s0 += acc[mf][nf][0] * acc[mf][nf][0] + acc[mf][nf][1] * acc[mf][nf][1];
                        s1 += acc[mf][nf][2] * acc[mf][nf][2] + acc[mf][nf][3] * acc[mf][nf][3];
                    }
                    s0 += __shfl_xor_sync(0xffffffffu, s0, 1);
                    s0 += __shfl_xor_sync(0xffffffffu, s0, 2);
                    s1 += __shfl_xor_sync(0xffffffffu, s1, 1);
                    s1 += __shfl_xor_sync(0xffffffffu, s1, 2);
                    if ((lane & 3) == 0) {
                        int r = wm * 32 + mf * 16 + (lane >> 2);
                        ssred[r * 4 + wn] = s0;
                        ssred[(r + 8) * 4 + wn] = s1;
                    }
                }
                __syncthreads();
#pragma unroll
                for (int mf = 0; mf < 2; mf++) {
                    int r = wm * 32 + mf * 16 + (lane >> 2);
                    float t0 = ssred[r * 4] + ssred[r * 4 + 1] + ssred[r * 4 + 2] + ssred[r * 4 + 3];
                    int r1 = r + 8;
                    float t1 = ssred[r1 * 4] + ssred[r1 * 4 + 1] + ssred[r1 * 4 + 2] + ssred[r1 * 4 + 3];
                    scale[mf][0] = 1.f / fmaxf(sqrtf(t0), 1e-12f);
                    scale[mf][1] = 1.f / fmaxf(sqrtf(t1), 1e-12f);
                }
            } else {
#pragma unroll
                for (int mf = 0; mf < 2; mf++) { scale[mf][0] = 1.f; scale[mf][1] = 1.f; }
            }
#pragma unroll
            for (int mf = 0; mf < 2; mf++)
#pragma unroll
                for (int hh = 0; hh < 2; hh++) {
                    int r = m0 + wm * 32 + mf * 16 + (lane >> 2) + hh * 8;
                    if (r < NN) {
#pragma unroll
                        for (int nf = 0; nf < 4; nf++) {
                            int col = wn * 32 + nf * 8 + (lane & 3) * 2;
                            float v0 = acc[mf][nf][2 * hh] * scale[mf][hh];
                            float v1 = acc[mf][nf][2 * hh + 1] * scale[mf][hh];
                            if (writeF) {
                                *(float2*)(outF + (size_t)r * HH + col) = make_float2(v0, v1);
                            }
                            __nv_bfloat162 hv, lv;
                            hv.x = __float2bfloat16(v0);
                            hv.y = __float2bfloat16(v1);
                            lv.x = __float2bfloat16(v0 - __bfloat162float(hv.x));
                            lv.y = __float2bfloat16(v1 - __bfloat162float(hv.y));
                            *(__nv_bfloat162*)(outH + (size_t)r * HH + col) = hv;
                            *(__nv_bfloat162*)(outL + (size_t)r * HH + col) = lv;
                        }
                    }
                }
#pragma unroll
            for (int mf = 0; mf < 2; mf++)
#pragma unroll
                for (int nf = 0; nf < 4; nf++)
#pragma unroll
                    for (int q = 0; q < 4; q++) acc[mf][nf][q] = 0.f;
        }
    }
}

// ---------------- global_add_pool (+ re-zero deg for next replay) ----------------
__global__ __launch_bounds__(128) void pool_kernel(const float* __restrict__ h,
                                                   const int* __restrict__ batch,
                                                   float* __restrict__ pool,
                                                   int* __restrict__ deg) {
    int gtid = blockIdx.x * 128 + threadIdx.x;
    for (int i = gtid; i < 3 * NN; i += gridDim.x * 128) deg[i] = 0;
    int c = threadIdx.x;
    int start = blockIdx.x * PCH;
    if (start >= NN) return;
    int end = min(start + PCH, NN);
    int cur = batch[start];
    float acc = 0.f;
    for (int i = start; i < end; ++i) {
        int b = batch[i];
        if (b != cur) { atomicAdd(&pool[cur * HH + c], acc); acc = 0.f; cur = b; }
        acc += h[(size_t)i * HH + c];
    }
    atomicAdd(&pool[cur * HH + c], acc);
}

// ---------------- MLP head ----------------
__global__ __launch_bounds__(256) void mlp_kernel(const float* __restrict__ pool,
                                                  const float* __restrict__ W0, const float* __restrict__ b0,
                                                  const float* __restrict__ W1, const float* __restrict__ b1,
                                                  const float* __restrict__ hW, const float* __restrict__ hb,
                                                  float* __restrict__ out) {
    __shared__ float Gs[GG * HH];
    int tid = threadIdx.x;
    for (int i = tid; i < GG * HH / 4; i += 256)
        ((float4*)Gs)[i] = ((const float4*)pool)[i];
    __syncthreads();
    int c = tid & 127;
    int rb = tid >> 7;
    float s[32];
#pragma unroll
    for (int j = 0; j < 32; j++) s[j] = b0[c];
    for (int k = 0; k < HH; k++) {
        float w = __ldg(W0 + k * HH + c);
#pragma unroll
        for (int j = 0; j < 32; j++) s[j] = fmaf(Gs[(rb + 2 * j) * HH + k], w, s[j]);
    }
    __syncthreads();
#pragma unroll
    for (int j = 0; j < 32; j++) Gs[(rb + 2 * j) * HH + c] = fmaxf(s[j], 0.f);
    __syncthreads();
#pragma unroll
    for (int j = 0; j < 32; j++) s[j] = b1[c];
    for (int k = 0; k < HH; k++) {
        float w = __ldg(W1 + k * HH + c);
#pragma unroll
        for (int j = 0; j < 32; j++) s[j] = fmaf(Gs[(rb + 2 * j) * HH + k], w, s[j]);
    }
    __syncthreads();
#pragma unroll
    for (int j = 0; j < 32; j++) Gs[(rb + 2 * j) * HH + c] = fmaxf(s[j], 0.f);
    __syncthreads();
    if (tid < GG) {
        float acc = hb[0];
        for (int k = 0; k < HH; k++) acc = fmaf(Gs[tid * HH + k], hW[k], acc);
        out[tid] = acc;
    }
}

// ---------------- driver ----------------
extern "C" void kernel_launch(void* const* d_in, const int* in_sizes, int n_in,
                              void* d_out, int out_size) {
    const float* x     = (const float*)d_in[0];
    const int*   eic   = (const int*)d_in[1];
    const int*   eid   = (const int*)d_in[2];
    const int*   eit   = (const int*)d_in[3];
    const int*   batch = (const int*)d_in[4];
    WPtrs wp;
    const float* bl[5];
    for (int i = 0; i < 5; i++) {
        wp.Wl[i] = (const float*)d_in[5 + 3 * i];
        bl[i]    = (const float*)d_in[6 + 3 * i];
        wp.Wr[i] = (const float*)d_in[7 + 3 * i];
    }
    const float* l0W   = (const float*)d_in[20];
    const float* l0b   = (const float*)d_in[21];
    const float* l1W   = (const float*)d_in[22];
    const float* l1b   = (const float*)d_in[23];
    const float* headW = (const float*)d_in[24];
    const float* headb = (const float*)d_in[25];

    void* p;
    cudaGetSymbolAddress(&p, g_bufA); float* bufA = (float*)p;
    cudaGetSymbolAddress(&p, g_pool); float* poolp = (float*)p;
    cudaGetSymbolAddress(&p, g_deg);  int* degp = (int*)p;
    cudaGetSymbolAddress(&p, g_csr);  int* csrp = (int*)p;
    cudaGetSymbolAddress(&p, g_hH);   __nv_bfloat16* hH = (__nv_bfloat16*)p;
    cudaGetSymbolAddress(&p, g_hL);   __nv_bfloat16* hL = (__nv_bfloat16*)p;
    cudaGetSymbolAddress(&p, g_aggH); __nv_bfloat16* aggH = (__nv_bfloat16*)p;
    cudaGetSymbolAddress(&p, g_aggL); __nv_bfloat16* aggL = (__nv_bfloat16*)p;
    cudaGetSymbolAddress(&p, g_wtb);  __nv_bfloat16* wtb = (__nv_bfloat16*)p;

    cudaFuncSetAttribute(sage_mma, cudaFuncAttributeMaxDynamicSharedMemorySize, SMEMSZ);

    size_t bufsz = (size_t)NN * HH;
    setup_kernel<<<CB + XB + WB, 256>>>(eid, eic, eit, wp, x,
                                        hH + bufsz, hL + bufsz, wtb, degp, csrp);  // 1
    zpool_kernel<<<GG * HH / 256, 256>>>(poolp);                                   // 2

    const int Les[7] = {0, 1, 1, 2, 0, 1, 1};
    const int Lcv[7] = {0, 1, 1, 2, 3, 4, 4};
    const int Lnm[7] = {1, 1, 1, 0, 1, 1, 1};

    for (int li = 0; li < 7; ++li) {
        int es = Les[li], cv = Lcv[li];
        int in = (li + 1) & 1, outi = li & 1;
        agg_kernel<<<(NN + 7) / 8, 256>>>(hH + (size_t)in * bufsz, hL + (size_t)in * bufsz,
                                          aggH, aggL,
                                          csrp + (size_t)es * NN * DCAP, degp + es * NN);
        sage_mma<<<148, 512, SMEMSZ>>>(
            aggH, aggL, hH + (size_t)in * bufsz, hL + (size_t)in * bufsz,
            wtb + (size_t)cv * 4 * HH * HH, bl[cv],
            bufA, hH + (size_t)outi * bufsz, hL + (size_t)outi * bufsz,
            Lnm[li], li == 6 ? 1 : 0);
    }

    pool_kernel<<<(NN + PCH - 1) / PCH, 128>>>(bufA, batch, poolp, degp);
    mlp_kernel<<<1, 256>>>(poolp, l0W, l0b, l1W, l1b, headW, headb, (float*)d_out);
}

// round 14
// speedup vs baseline: 1.0599x; 1.0403x over previous
#include <cuda_runtime.h>
#include <cuda_bf16.h>
#include <math.h>
#include <stdint.h>

#define NN 50000
#define EE 600000
#define HH 128
#define GG 64
#define PCH 64
#define DCAP 64
#define NTILES 391   // ceil(50000/128)

// ---- static device scratch ----
__device__ float g_bufA[(size_t)NN * HH];
__device__ float g_pool[GG * HH];
__device__ int   g_deg[3 * NN];                 // zeroed at load; re-zeroed by pool_kernel
__device__ int   g_csr[(size_t)3 * NN * DCAP];
__device__ __nv_bfloat16 g_hH[2][(size_t)NN * HH];
__device__ __nv_bfloat16 g_hL[2][(size_t)NN * HH];
__device__ __nv_bfloat16 g_aggH[(size_t)NN * HH];
__device__ __nv_bfloat16 g_aggL[(size_t)NN * HH];
// weights bf16: [conv 5][phase 2][hi/lo 2][n=128][k=128]
__device__ __nv_bfloat16 g_wtb[5 * 4 * HH * HH];

// ================= helpers =================
__device__ __forceinline__ uint32_t s2u(const void* p) {
    uint32_t a;
    asm("{ .reg .u64 t; cvta.to.shared.u64 t, %1; cvt.u32.u64 %0, t; }" : "=r"(a) : "l"(p));
    return a;
}
__device__ __forceinline__ void cpa16(uint32_t d, const void* s, uint32_t ssz) {
    asm volatile("cp.async.cg.shared.global [%0], [%1], 16, %2;"
                 :: "r"(d), "l"(s), "r"(ssz) : "memory");
}
__device__ __forceinline__ void cpa_commit() {
    asm volatile("cp.async.commit_group;" ::: "memory");
}
template <int N>
__device__ __forceinline__ void cpa_wait() {
    asm volatile("cp.async.wait_group %0;" :: "n"(N) : "memory");
}
#define LDSM4(r0, r1, r2, r3, a) \
    asm volatile("ldmatrix.sync.aligned.m8n8.x4.shared.b16 {%0,%1,%2,%3}, [%4];" \
                 : "=r"(r0), "=r"(r1), "=r"(r2), "=r"(r3) : "r"(a))
#define MMA_BF16(c, a, b) \
    asm volatile("mma.sync.aligned.m16n8k16.row.col.f32.bf16.bf16.f32 " \
                 "{%0,%1,%2,%3},{%4,%5,%6,%7},{%8,%9},{%0,%1,%2,%3};" \
                 : "+f"((c)[0]), "+f"((c)[1]), "+f"((c)[2]), "+f"((c)[3]) \
                 : "r"((a)[0]), "r"((a)[1]), "r"((a)[2]), "r"((a)[3]), \
                   "r"((b)[0]), "r"((b)[1]))

// smem: B 4x32KB @0, A 3 bufs x 32KB @131072, ssred @229376 (2KB)
#define SM_B 0
#define SM_A 131072
#define SM_SS 229376
#define SMEMSZ 231424

// ---------------- fused setup: bucketed CSR + x->bf16 hi/lo + weight prep + pool zero
struct WPtrs { const float* Wl[5]; const float* Wr[5]; };
#define CB 7032
#define XB 6250
#define WB 320
#define PB 32
__global__ __launch_bounds__(256) void setup_kernel(const int* __restrict__ e0,
                                                    const int* __restrict__ e1,
                                                    const int* __restrict__ e2,
                                                    WPtrs wp,
                                                    const float* __restrict__ x,
                                                    __nv_bfloat16* __restrict__ oh,
                                                    __nv_bfloat16* __restrict__ ol,
                                                    __nv_bfloat16* __restrict__ wtb,
                                                    int* __restrict__ deg,
                                                    int* __restrict__ csr,
                                                    float* __restrict__ poolp) {
    int b = blockIdx.x, tid = threadIdx.x;
    if (b < CB) {
        int t = b * 256 + tid;
        if (t < 3 * EE) {
            int s = t / EE, i = t - s * EE;
            const int* e = (s == 0) ? e0 : ((s == 1) ? e1 : e2);
            int dst = e[EE + i];
            int p = atomicAdd(&deg[s * NN + dst], 1);
            if (p < DCAP) csr[((size_t)s * NN + dst) * DCAP + p] = e[i];
        }
    } else if (b < CB + XB) {
        int i = (b - CB) * 256 + tid;
        float4 v = ((const float4*)x)[i];
        __nv_bfloat162 h01, h23, l01, l23;
        h01.x = __float2bfloat16(v.x); l01.x = __float2bfloat16(v.x - __bfloat162float(h01.x));
        h01.y = __float2bfloat16(v.y); l01.y = __float2bfloat16(v.y - __bfloat162float(h01.y));
        h23.x = __float2bfloat16(v.z); l23.x = __float2bfloat16(v.z - __bfloat162float(h23.x));
        h23.y = __float2bfloat16(v.w); l23.y = __float2bfloat16(v.w - __bfloat162float(h23.y));
        ((__nv_bfloat162*)oh)[i * 2] = h01; ((__nv_bfloat162*)oh)[i * 2 + 1] = h23;
        ((__nv_bfloat162*)ol)[i * 2] = l01; ((__nv_bfloat162*)ol)[i * 2 + 1] = l23;
    } else if (b < CB + XB + WB) {
        int idx = (b - CB - XB) * 256 + tid;
        int cv = idx >> 14, rem = idx & 16383;
        int n = rem >> 7, k = rem & 127;
        __nv_bfloat16* base = wtb + (size_t)cv * 4 * HH * HH;
        float a = wp.Wl[cv][k * HH + n];
        __nv_bfloat16 ah = __float2bfloat16(a);
        base[n * HH + k] = ah;
        base[HH * HH + n * HH + k] = __float2bfloat16(a - __bfloat162float(ah));
        float w = wp.Wr[cv][k * HH + n];
        __nv_bfloat16 bh = __float2bfloat16(w);
        base[2 * HH * HH + n * HH + k] = bh;
        base[3 * HH * HH + n * HH + k] = __float2bfloat16(w - __bfloat162float(bh));
    } else {
        int g = (b - CB - XB - WB) * 256 + tid;
        if (g < GG * HH) poolp[g] = 0.f;
    }
}

// ---------------- mean aggregation v2: fp32 gather (lane owns 4 cols) ----------------
__global__ __launch_bounds__(256) void agg_kernel(const float* __restrict__ fsrc,
                                                  __nv_bfloat16* __restrict__ aggH,
                                                  __nv_bfloat16* __restrict__ aggL,
                                                  const int* __restrict__ csr,
                                                  const int* __restrict__ deg) {
    int node = blockIdx.x * 8 + (threadIdx.x >> 5);
    if (node >= NN) return;
    int lane = threadIdx.x & 31;
    int co = lane * 4;
    int d = deg[node];
    int dr = min(d, DCAP);
    const int* nb = csr + (size_t)node * DCAP;
    float4 acc = make_float4(0.f, 0.f, 0.f, 0.f);

    int p = 0;
    for (; p + 4 <= dr; p += 4) {
        int4 iv = *(const int4*)(nb + p);
        float4 v0 = *(const float4*)(fsrc + (size_t)iv.x * HH + co);
        float4 v1 = *(const float4*)(fsrc + (size_t)iv.y * HH + co);
        float4 v2 = *(const float4*)(fsrc + (size_t)iv.z * HH + co);
        float4 v3 = *(const float4*)(fsrc + (size_t)iv.w * HH + co);
        acc.x += v0.x + v1.x + v2.x + v3.x;
        acc.y += v0.y + v1.y + v2.y + v3.y;
        acc.z += v0.z + v1.z + v2.z + v3.z;
        acc.w += v0.w + v1.w + v2.w + v3.w;
    }
    for (; p < dr; ++p) {
        float4 v0 = *(const float4*)(fsrc + (size_t)nb[p] * HH + co);
        acc.x += v0.x; acc.y += v0.y; acc.z += v0.z; acc.w += v0.w;
    }
    float inv = 1.f / fmaxf((float)d, 1.f);
    acc.x *= inv; acc.y *= inv; acc.z *= inv; acc.w *= inv;

    __nv_bfloat162 h01, h23, l01, l23;
    h01.x = __float2bfloat16(acc.x); l01.x = __float2bfloat16(acc.x - __bfloat162float(h01.x));
    h01.y = __float2bfloat16(acc.y); l01.y = __float2bfloat16(acc.y - __bfloat162float(h01.y));
    h23.x = __float2bfloat16(acc.z); l23.x = __float2bfloat16(acc.z - __bfloat162float(h23.x));
    h23.y = __float2bfloat16(acc.w); l23.y = __float2bfloat16(acc.w - __bfloat162float(h23.y));
    uint2 ho, lo;
    ho.x = *(uint32_t*)&h01; ho.y = *(uint32_t*)&h23;
    lo.x = *(uint32_t*)&l01; lo.y = *(uint32_t*)&l23;
    *(uint2*)(aggH + (size_t)node * HH + co) = ho;
    *(uint2*)(aggL + (size_t)node * HH + co) = lo;
}

// ---------------- persistent bf16-split tensor-core SAGE GEMM, 512 threads ----------------
__global__ __launch_bounds__(512) void sage_mma(const __nv_bfloat16* __restrict__ aggH,
                                                const __nv_bfloat16* __restrict__ aggL,
                                                const __nv_bfloat16* __restrict__ hinH,
                                                const __nv_bfloat16* __restrict__ hinL,
                                                const __nv_bfloat16* __restrict__ wb,
                                                const float* __restrict__ bias,
                                                float* __restrict__ outF,
                                                __nv_bfloat16* __restrict__ outH,
                                                __nv_bfloat16* __restrict__ outL,
                                                int doNorm, int writeB) {
    extern __shared__ char smem[];
    const uint32_t sb = s2u(smem);
    const int tid = threadIdx.x;
    const int wid = tid >> 5, lane = tid & 31;
    const int wm = wid >> 2, wn = wid & 3;
    const int bid = blockIdx.x;
    const int nch = 4 * ((NTILES - bid + 147) / 148);

    // B load: 4 matrices x 32KB, swizzled [n][256B rows]
#pragma unroll
    for (int i = 0; i < 16; i++) {
        int idx = tid + i * 512;
        int a = idx >> 11, u = idx & 2047;
        int n = u >> 4, kunit = u & 15;
        uint32_t off = (uint32_t)(n * 256 + kunit * 16);
        uint32_t sw = off ^ ((off >> 4) & 0x70);
        cpa16(sb + SM_B + a * 32768 + sw, wb + (size_t)idx * 8, 16u);
    }
    auto issueA = [&](int ch) {
        int tile = bid + (ch >> 2) * 148;
        int c = ch & 3, buf = ch % 3;
        int m0 = tile * 128;
        const __nv_bfloat16* sH = (c < 2) ? aggH : hinH;
        const __nv_bfloat16* sL = (c < 2) ? aggL : hinL;
        int koff = (c & 1) * 64;
#pragma unroll
        for (int i = 0; i < 2; i++) {
            int idx = tid + i * 512;
            int r = idx >> 3, ku = idx & 7;
            int gm = m0 + r;
            uint32_t off = (uint32_t)(r * 128 + ku * 16);
            uint32_t sw = off ^ ((off >> 3) & 0x70);
            uint32_t ssz = (gm < NN) ? 16u : 0u;
            int gmc = (gm < NN) ? gm : 0;
            cpa16(sb + SM_A + buf * 32768 + sw,         sH + (size_t)gmc * HH + koff + ku * 8, ssz);
            cpa16(sb + SM_A + buf * 32768 + 16384 + sw, sL + (size_t)gmc * HH + koff + ku * 8, ssz);
        }
    };
    issueA(0); cpa_commit();
    issueA(1); cpa_commit();

    float acc[2][4][4];
#pragma unroll
    for (int mf = 0; mf < 2; mf++)
#pragma unroll
        for (int nf = 0; nf < 4; nf++)
#pragma unroll
            for (int q = 0; q < 4; q++) acc[mf][nf][q] = 0.f;

    float* ssred = (float*)(smem + SM_SS);
    float bc[4][2];
#pragma unroll
    for (int nf = 0; nf < 4; nf++) {
        int col = wn * 32 + nf * 8 + (lane & 3) * 2;
        bc[nf][0] = __ldg(bias + col);
        bc[nf][1] = __ldg(bias + col + 1);
    }

    const uint32_t rAl = (uint32_t)(wm * 32 + (lane & 15));
    const uint32_t kAl = (uint32_t)((lane >> 4) * 16);
    const uint32_t nBl = (uint32_t)(wn * 32 + ((lane >> 4) << 3) + (lane & 7));
    const uint32_t kBl = (uint32_t)(((lane >> 3) & 1) * 16);

    for (int ch = 0; ch < nch; ch++) {
        if (ch + 2 < nch) cpa_wait<1>(); else cpa_wait<0>();
        __syncthreads();
        if (ch + 2 < nch) { issueA(ch + 2); cpa_commit(); }

        const int buf = ch % 3, c = ch & 3, ph = c >> 1;
        const uint32_t Ah = sb + SM_A + buf * 32768;
        const uint32_t Al = Ah + 16384;
        const uint32_t Bh = sb + SM_B + (ph * 2 + 0) * 32768;
        const uint32_t Bl = sb + SM_B + (ph * 2 + 1) * 32768;
        const uint32_t kbB0 = (uint32_t)((c & 1) * 128);
#pragma unroll
        for (int kc = 0; kc < 4; kc++) {
            uint32_t kbA = kc * 32 + kAl;
            uint32_t kbB = kbB0 + kc * 32 + kBl;
            uint32_t ah[2][4], al[2][4];
#pragma unroll
            for (int mf = 0; mf < 2; mf++) {
                uint32_t off = (rAl + mf * 16) * 128 + kbA;
                uint32_t sw = off ^ ((off >> 3) & 0x70);
                LDSM4(ah[mf][0], ah[mf][1], ah[mf][2], ah[mf][3], Ah + sw);
                LDSM4(al[mf][0], al[mf][1], al[mf][2], al[mf][3], Al + sw);
            }
            uint32_t bh[4][2], bl[4][2];
#pragma unroll
            for (int np = 0; np < 2; np++) {
                uint32_t off = (nBl + np * 16) * 256 + kbB;
                uint32_t sw = off ^ ((off >> 4) & 0x70);
                uint32_t r0, r1, r2, r3;
                LDSM4(r0, r1, r2, r3, Bh + sw);
                bh[2 * np][0] = r0; bh[2 * np][1] = r1;
                bh[2 * np + 1][0] = r2; bh[2 * np + 1][1] = r3;
                LDSM4(r0, r1, r2, r3, Bl + sw);
                bl[2 * np][0] = r0; bl[2 * np][1] = r1;
                bl[2 * np + 1][0] = r2; bl[2 * np + 1][1] = r3;
            }
#pragma unroll
            for (int mf = 0; mf < 2; mf++)
#pragma unroll
                for (int nf = 0; nf < 4; nf++) {
                    MMA_BF16(acc[mf][nf], ah[mf], bh[nf]);
                    MMA_BF16(acc[mf][nf], ah[mf], bl[nf]);
                    MMA_BF16(acc[mf][nf], al[mf], bh[nf]);
                }
        }

        if ((ch & 3) == 3) {
            // ---------------- epilogue for this tile ----------------
            int m0 = (bid + (ch >> 2) * 148) * 128;
#pragma unroll
            for (int mf = 0; mf < 2; mf++)
#pragma unroll
                for (int nf = 0; nf < 4; nf++) {
                    acc[mf][nf][0] += bc[nf][0];
                    acc[mf][nf][1] += bc[nf][1];
                    acc[mf][nf][2] += bc[nf][0];
                    acc[mf][nf][3] += bc[nf][1];
                }
            float scale[2][2];
            if (doNorm) {
#pragma unroll
                for (int mf = 0; mf < 2; mf++) {
                    float s0 = 0.f, s1 = 0.f;
#pragma unroll
                    for (int nf = 0; nf < 4; nf++) {
                        s0 += acc[mf][nf][0] * acc[mf][nf][0] + acc[mf][nf][1] * acc[mf][nf][1];
                        s1 += acc[mf][nf][2] * acc[mf][nf][2] + acc[mf][nf][3] * acc[mf][nf][3];
                    }
                    s0 += __shfl_xor_sync(0xffffffffu, s0, 1);
                    s0 += __shfl_xor_sync(0xffffffffu, s0, 2);
                    s1 += __shfl_xor_sync(0xffffffffu, s1, 1);
                    s1 += __shfl_xor_sync(0xffffffffu, s1, 2);
                    if ((lane & 3) == 0) {
                        int r = wm * 32 + mf * 16 + (lane >> 2);
                        ssred[r * 4 + wn] = s0;
                        ssred[(r + 8) * 4 + wn] = s1;
                    }
                }
                __syncthreads();
#pragma unroll
                for (int mf = 0; mf < 2; mf++) {
                    int r = wm * 32 + mf * 16 + (lane >> 2);
                    float t0 = ssred[r * 4] + ssred[r * 4 + 1] + ssred[r * 4 + 2] + ssred[r * 4 + 3];
                    int r1 = r + 8;
                    float t1 = ssred[r1 * 4] + ssred[r1 * 4 + 1] + ssred[r1 * 4 + 2] + ssred[r1 * 4 + 3];
                    scale[mf][0] = 1.f / fmaxf(sqrtf(t0), 1e-12f);
                    scale[mf][1] = 1.f / fmaxf(sqrtf(t1), 1e-12f);
                }
            } else {
#pragma unroll
                for (int mf = 0; mf < 2; mf++) { scale[mf][0] = 1.f; scale[mf][1] = 1.f; }
            }
#pragma unroll
            for (int mf = 0; mf < 2; mf++)
#pragma unroll
                for (int hh = 0; hh < 2; hh++) {
                    int r = m0 + wm * 32 + mf * 16 + (lane >> 2) + hh * 8;
                    if (r < NN) {
#pragma unroll
                        for (int nf = 0; nf < 4; nf++) {
                            int col = wn * 32 + nf * 8 + (lane & 3) * 2;
                            float v0 = acc[mf][nf][2 * hh] * scale[mf][hh];
                            float v1 = acc[mf][nf][2 * hh + 1] * scale[mf][hh];
                            *(float2*)(outF + (size_t)r * HH + col) = make_float2(v0, v1);
                            if (writeB) {
                                __nv_bfloat162 hv, lv;
                                hv.x = __float2bfloat16(v0);
                                hv.y = __float2bfloat16(v1);
                                lv.x = __float2bfloat16(v0 - __bfloat162float(hv.x));
                                lv.y = __float2bfloat16(v1 - __bfloat162float(hv.y));
                                *(__nv_bfloat162*)(outH + (size_t)r * HH + col) = hv;
                                *(__nv_bfloat162*)(outL + (size_t)r * HH + col) = lv;
                            }
                        }
                    }
                }
#pragma unroll
            for (int mf = 0; mf < 2; mf++)
#pragma unroll
                for (int nf = 0; nf < 4; nf++)
#pragma unroll
                    for (int q = 0; q < 4; q++) acc[mf][nf][q] = 0.f;
        }
    }
}

// ---------------- global_add_pool (+ re-zero deg for next replay) ----------------
__global__ __launch_bounds__(128) void pool_kernel(const float* __restrict__ h,
                                                   const int* __restrict__ batch,
                                                   float* __restrict__ pool,
                                                   int* __restrict__ deg) {
    int gtid = blockIdx.x * 128 + threadIdx.x;
    for (int i = gtid; i < 3 * NN; i += gridDim.x * 128) deg[i] = 0;
    int c = threadIdx.x;
    int start = blockIdx.x * PCH;
    if (start >= NN) return;
    int end = min(start + PCH, NN);
    int cur = batch[start];
    float acc = 0.f;
    for (int i = start; i < end; ++i) {
        int b = batch[i];
        if (b != cur) { atomicAdd(&pool[cur * HH + c], acc); acc = 0.f; cur = b; }
        acc += h[(size_t)i * HH + c];
    }
    atomicAdd(&pool[cur * HH + c], acc);
}

// ---------------- MLP head ----------------
__global__ __launch_bounds__(256) void mlp_kernel(const float* __restrict__ pool,
                                                  const float* __restrict__ W0, const float* __restrict__ b0,
                                                  const float* __restrict__ W1, const float* __restrict__ b1,
                                                  const float* __restrict__ hW, const float* __restrict__ hb,
                                                  float* __restrict__ out) {
    __shared__ float Gs[GG * HH];
    int tid = threadIdx.x;
    for (int i = tid; i < GG * HH / 4; i += 256)
        ((float4*)Gs)[i] = ((const float4*)pool)[i];
    __syncthreads();
    int c = tid & 127;
    int rb = tid >> 7;
    float s[32];
#pragma unroll
    for (int j = 0; j < 32; j++) s[j] = b0[c];
    for (int k = 0; k < HH; k++) {
        float w = __ldg(W0 + k * HH + c);
#pragma unroll
        for (int j = 0; j < 32; j++) s[j] = fmaf(Gs[(rb + 2 * j) * HH + k], w, s[j]);
    }
    __syncthreads();
#pragma unroll
    for (int j = 0; j < 32; j++) Gs[(rb + 2 * j) * HH + c] = fmaxf(s[j], 0.f);
    __syncthreads();
#pragma unroll
    for (int j = 0; j < 32; j++) s[j] = b1[c];
    for (int k = 0; k < HH; k++) {
        float w = __ldg(W1 + k * HH + c);
#pragma unroll
        for (int j = 0; j < 32; j++) s[j] = fmaf(Gs[(rb + 2 * j) * HH + k], w, s[j]);
    }
    __syncthreads();
#pragma unroll
    for (int j = 0; j < 32; j++) Gs[(rb + 2 * j) * HH + c] = fmaxf(s[j], 0.f);
    __syncthreads();
    if (tid < GG) {
        float acc = hb[0];
        for (int k = 0; k < HH; k++) acc = fmaf(Gs[tid * HH + k], hW[k], acc);
        out[tid] = acc;
    }
}

// ---------------- driver ----------------
extern "C" void kernel_launch(void* const* d_in, const int* in_sizes, int n_in,
                              void* d_out, int out_size) {
    const float* x     = (const float*)d_in[0];
    const int*   eic   = (const int*)d_in[1];
    const int*   eid   = (const int*)d_in[2];
    const int*   eit   = (const int*)d_in[3];
    const int*   batch = (const int*)d_in[4];
    WPtrs wp;
    const float* bl[5];
    for (int i = 0; i < 5; i++) {
        wp.Wl[i] = (const float*)d_in[5 + 3 * i];
        bl[i]    = (const float*)d_in[6 + 3 * i];
        wp.Wr[i] = (const float*)d_in[7 + 3 * i];
    }
    const float* l0W   = (const float*)d_in[20];
    const float* l0b   = (const float*)d_in[21];
    const float* l1W   = (const float*)d_in[22];
    const float* l1b   = (const float*)d_in[23];
    const float* headW = (const float*)d_in[24];
    const float* headb = (const float*)d_in[25];

    void* p;
    cudaGetSymbolAddress(&p, g_bufA); float* bufA = (float*)p;
    cudaGetSymbolAddress(&p, g_pool); float* poolp = (float*)p;
    cudaGetSymbolAddress(&p, g_deg);  int* degp = (int*)p;
    cudaGetSymbolAddress(&p, g_csr);  int* csrp = (int*)p;
    cudaGetSymbolAddress(&p, g_hH);   __nv_bfloat16* hH = (__nv_bfloat16*)p;
    cudaGetSymbolAddress(&p, g_hL);   __nv_bfloat16* hL = (__nv_bfloat16*)p;
    cudaGetSymbolAddress(&p, g_aggH); __nv_bfloat16* aggH = (__nv_bfloat16*)p;
    cudaGetSymbolAddress(&p, g_aggL); __nv_bfloat16* aggL = (__nv_bfloat16*)p;
    cudaGetSymbolAddress(&p, g_wtb);  __nv_bfloat16* wtb = (__nv_bfloat16*)p;

    cudaFuncSetAttribute(sage_mma, cudaFuncAttributeMaxDynamicSharedMemorySize, SMEMSZ);

    size_t bufsz = (size_t)NN * HH;
    // launch 1: setup (CSR + x->bf16 slot1 + weights + pool zero)
    setup_kernel<<<CB + XB + WB + PB, 256>>>(eid, eic, eit, wp, x,
                                             hH + bufsz, hL + bufsz, wtb, degp, csrp, poolp);

    const int Les[7] = {0, 1, 1, 2, 0, 1, 1};
    const int Lcv[7] = {0, 1, 1, 2, 3, 4, 4};
    const int Lnm[7] = {1, 1, 1, 0, 1, 1, 1};

    const float* curF = x;   // fp32 feature source for agg (layer 0: x itself)
    for (int li = 0; li < 7; ++li) {
        int es = Les[li], cv = Lcv[li];
        int in = (li + 1) & 1, outi = li & 1;
        agg_kernel<<<(NN + 7) / 8, 256>>>(curF, aggH, aggL,
                                          csrp + (size_t)es * NN * DCAP, degp + es * NN);
        sage_mma<<<148, 512, SMEMSZ>>>(
            aggH, aggL, hH + (size_t)in * bufsz, hL + (size_t)in * bufsz,
            wtb + (size_t)cv * 4 * HH * HH, bl[cv],
            bufA, hH + (size_t)outi * bufsz, hL + (size_t)outi * bufsz,
            Lnm[li], li == 6 ? 0 : 1);
        curF = bufA;
    }

    pool_kernel<<<(NN + PCH - 1) / PCH, 128>>>(bufA, batch, poolp, degp);
    mlp_kernel<<<1, 256>>>(poolp, l0W, l0b, l1W, l1b, headW, headb, (float*)d_out);
}